// round 7
// baseline (speedup 1.0000x reference)
#include <cuda_runtime.h>
#include <cuda_bf16.h>

#define BMAX 32
#define NMAX 640
#define GMAX 512        // max frame-groups per batch
#define TB   8          // frames per block
#define NT   96         // threads per block (E = 384 = 4*NT)

// ---- packed f32x2 helpers (sm_103a) ----
__device__ __forceinline__ unsigned long long pack2(float lo, float hi) {
    unsigned long long r;
    asm("mov.b64 %0, {%1, %2};" : "=l"(r) : "f"(lo), "f"(hi));
    return r;
}
__device__ __forceinline__ void unpack2(unsigned long long v, float& lo, float& hi) {
    asm("mov.b64 {%0, %1}, %2;" : "=f"(lo), "=f"(hi) : "l"(v));
}
__device__ __forceinline__ unsigned long long fma2(unsigned long long a,
                                                   unsigned long long b,
                                                   unsigned long long c) {
    unsigned long long r;
    asm("fma.rn.f32x2 %0, %1, %2, %3;" : "=l"(r) : "l"(a), "l"(b), "l"(c));
    return r;
}
__device__ __forceinline__ unsigned long long add2(unsigned long long a,
                                                   unsigned long long b) {
    unsigned long long r;
    asm("add.rn.f32x2 %0, %1, %2;" : "=l"(r) : "l"(a), "l"(b));
    return r;
}

// Scratch (allocation-free rule: __device__ globals)
__device__ float g_c[BMAX][NMAX];      // compacted token centers
__device__ float g_rsig[BMAX][NMAX];   // 1/sigma
__device__ float g_coef[BMAX][NMAX];   // 1/(sigma*sqrt(2pi))
__device__ int   g_tok[BMAX][NMAX];    // merged token ids (compacted)
__device__ float g_cumtot[BMAX];       // total duration per batch
__device__ int2  g_win[BMAX][GMAX];    // per frame-group token window [nlo, nhi]

// ---------------------------------------------------------------------------
// Kernel 1 (fused): merge pairs + shuffle-scan cumsum + compaction of
// zero-weight tokens (pad or zero-duration contribute EXACTLY 0 weight:
// sigma=1e-6 gives |z|>=5e5 so expf underflows to 0 in fp32, matching the
// reference's own underflow) + per-group window binary search in shared mem.
// One block per batch, 1024 threads.
// ---------------------------------------------------------------------------
__global__ void __launch_bounds__(1024)
prep_kernel(const int* __restrict__ text,
            const int* __restrict__ durs,
            int L, int N, int G) {
    const int b    = blockIdx.x;
    const int tid  = threadIdx.x;
    const int wrp  = tid >> 5;
    const int lane = tid & 31;

    float dm = 0.f;
    int   tk = 0;
    if (tid < N) {
        if (tid == 0) {
            dm = (float)durs[b * L];
            tk = text[b * L];
        } else {
            dm = (float)(durs[b * L + 2 * tid - 1] + durs[b * L + 2 * tid]);
            tk = text[b * L + 2 * tid - 1];
        }
    }
    const int keep = (tid < N && tk != 0 && dm > 0.f) ? 1 : 0;

    // ---- two-level inclusive scan over (dm, keep) via shuffles ----
    __shared__ float s_wd[32];
    __shared__ int   s_wk[32];
    float cum = dm;
    int   pos = keep;
    #pragma unroll
    for (int off = 1; off < 32; off <<= 1) {
        float fv = __shfl_up_sync(0xffffffffu, cum, off);
        int   iv = __shfl_up_sync(0xffffffffu, pos, off);
        if (lane >= off) { cum += fv; pos += iv; }
    }
    if (lane == 31) { s_wd[wrp] = cum; s_wk[wrp] = pos; }
    __syncthreads();
    if (wrp == 0) {
        float fv = s_wd[lane];
        int   iv = s_wk[lane];
        #pragma unroll
        for (int off = 1; off < 32; off <<= 1) {
            float f2 = __shfl_up_sync(0xffffffffu, fv, off);
            int   i2 = __shfl_up_sync(0xffffffffu, iv, off);
            if (lane >= off) { fv += f2; iv += i2; }
        }
        s_wd[lane] = fv; s_wk[lane] = iv;
    }
    __syncthreads();
    if (wrp > 0) { cum += s_wd[wrp - 1]; pos += s_wk[wrp - 1]; }

    // ---- emit compacted token params ----
    __shared__ float s_c[NMAX];
    __shared__ int   s_n2;
    if (keep) {
        const int   o   = pos - 1;
        const float sig = dm * 0.5f + 1e-6f;     // d / SIGMA_C + EPS, SIGMA_C = 2
        const float c   = cum - 0.5f * dm;
        g_c[b][o]    = c;
        g_rsig[b][o] = 1.0f / sig;
        g_coef[b][o] = 0.3989422804014327f / sig;
        g_tok[b][o]  = tk;
        s_c[o]       = c;
    }
    if (tid == N - 1) { g_cumtot[b] = cum; s_n2 = pos; }
    __syncthreads();

    // ---- per frame-group windows via binary search in shared centers ----
    // Window |t-c| <= 18: truncated tokens contribute <= ~1e-7 relative
    // (every valid frame has a contributor within ~6 frames, w >= 0.018).
    if (tid < G) {
        const int   N2  = s_n2;
        const float t0f = (float)(tid * TB);
        const float tlo = t0f + 0.5f - 18.f;
        const float thi = t0f + ((float)TB - 0.5f) + 18.f;
        int lo = 0, hi = N2;
        while (lo < hi) { int m = (lo + hi) >> 1; if (s_c[m] < tlo) lo = m + 1; else hi = m; }
        const int nlo = lo;
        hi = N2;
        while (lo < hi) { int m = (lo + hi) >> 1; if (s_c[m] <= thi) lo = m + 1; else hi = m; }
        g_win[b][tid] = make_int2(nlo, lo - 1);
    }
}

// ---------------------------------------------------------------------------
// Kernel 2: one block per (b, 8 frames). 96 threads; thread owns ONE float4
// of the embedding dim (E = 384 = 96*4). Accumulators are f32x2 frame-pairs:
// acc[d][p] holds frames {2p, 2p+1} for dim d. 16 FFMA2 per token = 32 FMAs.
// Raw weights; per-frame sums accumulated redundantly; normalize at the end.
// ---------------------------------------------------------------------------
__global__ void __launch_bounds__(NT)
lenreg_kernel(const float* __restrict__ emb,
              float* __restrict__ out,
              int T) {
    const int b   = blockIdx.y;
    const int t0  = blockIdx.x * TB;
    const int tid = threadIdx.x;

    float4* obase4 = (float4*)(out + ((size_t)b * T + t0) * 384);
    const float cumtot = g_cumtot[b];

    // Entire block beyond sample duration -> zeros and exit (~25% of blocks)
    if ((float)t0 + 0.5f >= cumtot) {
        const float4 z = make_float4(0.f, 0.f, 0.f, 0.f);
        #pragma unroll
        for (int tt = 0; tt < TB; tt++) obase4[tt * NT + tid] = z;
        return;
    }

    const float* __restrict__ cb    = g_c[b];
    const float* __restrict__ rsigb = g_rsig[b];
    const float* __restrict__ coefb = g_coef[b];
    const int*   __restrict__ tokb  = g_tok[b];

    const int2  win = g_win[b][blockIdx.x];
    const int   nlo = win.x;
    const int   nhi = win.y;
    const float t0f = (float)t0;

    __shared__ ulonglong2 Wt[NT * 2];  // [token][pair/2]: 4 packed f32x2 weights
    __shared__ int        off_s[NT];   // byte offsets into emb table

    unsigned long long acc[4][4];      // [dim][frame-pair]
    unsigned long long ws2[4];         // packed per-frame weight sums
    #pragma unroll
    for (int d = 0; d < 4; d++)
        #pragma unroll
        for (int p = 0; p < 4; p++) acc[d][p] = 0ull;
    #pragma unroll
    for (int p = 0; p < 4; p++) ws2[p] = 0ull;

    for (int base = nlo; base <= nhi; base += NT) {
        const int n = base + tid;
        // ---- stage packed raw weights for own token ----
        if (n <= nhi) {
            const float c  = cb[n];
            const float rs = rsigb[n];
            const float cf = coefb[n];
            float w[TB];
            #pragma unroll
            for (int tt = 0; tt < TB; tt++) {
                float z = (t0f + (float)tt + 0.5f - c) * rs;
                w[tt] = cf * __expf(-0.5f * z * z);
            }
            Wt[tid * 2 + 0] = make_ulonglong2(pack2(w[0], w[1]), pack2(w[2], w[3]));
            Wt[tid * 2 + 1] = make_ulonglong2(pack2(w[4], w[5]), pack2(w[6], w[7]));
            off_s[tid] = tokb[n] * 1536;   // *384 floats *4 bytes
        }
        __syncthreads();

        const int cnt = min(NT, nhi - base + 1);

        // ---- accumulate: 16 FFMA2 + 4 ADD2 per token against 1 LDG.128 ----
        #pragma unroll 2
        for (int j = 0; j < cnt; j++) {
            const float4 e = *(const float4*)((const char*)emb + off_s[j] + (tid << 4));
            const ulonglong2 wa = Wt[j * 2 + 0];
            const ulonglong2 wb = Wt[j * 2 + 1];
            const unsigned long long ex = pack2(e.x, e.x);
            const unsigned long long ey = pack2(e.y, e.y);
            const unsigned long long ez = pack2(e.z, e.z);
            const unsigned long long ew = pack2(e.w, e.w);
            ws2[0] = add2(ws2[0], wa.x);
            ws2[1] = add2(ws2[1], wa.y);
            ws2[2] = add2(ws2[2], wb.x);
            ws2[3] = add2(ws2[3], wb.y);
            acc[0][0] = fma2(ex, wa.x, acc[0][0]);
            acc[0][1] = fma2(ex, wa.y, acc[0][1]);
            acc[0][2] = fma2(ex, wb.x, acc[0][2]);
            acc[0][3] = fma2(ex, wb.y, acc[0][3]);
            acc[1][0] = fma2(ey, wa.x, acc[1][0]);
            acc[1][1] = fma2(ey, wa.y, acc[1][1]);
            acc[1][2] = fma2(ey, wb.x, acc[1][2]);
            acc[1][3] = fma2(ey, wb.y, acc[1][3]);
            acc[2][0] = fma2(ez, wa.x, acc[2][0]);
            acc[2][1] = fma2(ez, wa.y, acc[2][1]);
            acc[2][2] = fma2(ez, wb.x, acc[2][2]);
            acc[2][3] = fma2(ez, wb.y, acc[2][3]);
            acc[3][0] = fma2(ew, wa.x, acc[3][0]);
            acc[3][1] = fma2(ew, wa.y, acc[3][1]);
            acc[3][2] = fma2(ew, wb.x, acc[3][2]);
            acc[3][3] = fma2(ew, wb.y, acc[3][3]);
        }
        if (base + NT <= nhi) __syncthreads();   // only if another chunk follows
    }

    // ---- deferred normalization + stores (1 STG.128 per frame) ----
    #pragma unroll
    for (int p = 0; p < 4; p++) {
        float s0, s1;
        unpack2(ws2[p], s0, s1);
        const int f0 = 2 * p, f1 = 2 * p + 1;
        const float inv0 = ((t0f + (float)f0 + 0.5f) < cumtot) ? 1.0f / (s0 + 1e-6f) : 0.f;
        const float inv1 = ((t0f + (float)f1 + 0.5f) < cumtot) ? 1.0f / (s1 + 1e-6f) : 0.f;
        float lo0, hi0, lo1, hi1, lo2, hi2, lo3, hi3;
        unpack2(acc[0][p], lo0, hi0);
        unpack2(acc[1][p], lo1, hi1);
        unpack2(acc[2][p], lo2, hi2);
        unpack2(acc[3][p], lo3, hi3);
        obase4[f0 * NT + tid] = make_float4(lo0 * inv0, lo1 * inv0, lo2 * inv0, lo3 * inv0);
        obase4[f1 * NT + tid] = make_float4(hi0 * inv1, hi1 * inv1, hi2 * inv1, hi3 * inv1);
    }
}

// ---------------------------------------------------------------------------
extern "C" void kernel_launch(void* const* d_in, const int* in_sizes, int n_in,
                              void* d_out, int out_size) {
    const int*   text = (const int*)d_in[0];
    const int*   durs = (const int*)d_in[1];
    const float* emb  = (const float*)d_in[2];
    float* out = (float*)d_out;

    const int B = 32;
    const int L = in_sizes[0] / B;        // 1025
    const int N = (L + 1) / 2;            // 513
    const int T = out_size / (B * 384);   // 2048
    const int G = T / TB;                 // 256 frame-groups per batch

    prep_kernel<<<B, 1024>>>(text, durs, L, N, G);

    dim3 grid(G, B);
    lenreg_kernel<<<grid, NT>>>(emb, out, T);
}